// round 11
// baseline (speedup 1.0000x reference)
#include <cuda_runtime.h>
#include <cstdint>
#include <cstddef>

// Problem constants
#define BB     8
#define NN     2048
#define FF     256
#define LRA    0.2f
#define NSPLIT 4      // KV splits per row-tile
#define JT     8      // j-tiles per split (32 total / NSPLIT)

typedef unsigned long long ULL;

// ---------------- scratch (device globals: no allocations allowed) ------------
__device__ float g_Wh[BB * NN * FF];             // 16 MB
__device__ float g_s1[BB * NN];
__device__ float g_s2[BB * NN];
__device__ float g_Wt[FF * FF];                  // W transposed
__device__ float g_pacc[NSPLIT][BB * NN][FF];    // 64 MB unnormalized partials
__device__ float g_pm[NSPLIT][BB * NN];          // partial row max
__device__ float g_pl[NSPLIT][BB * NN];          // partial row sum

// ---------------- f32x2 helpers ----------------------------------------------
__device__ __forceinline__ ULL dup_f32(float x) {
    ULL r; unsigned u = __float_as_uint(x);
    asm("mov.b64 %0, {%1, %1};" : "=l"(r) : "r"(u));
    return r;
}
__device__ __forceinline__ void fma2(ULL& d, ULL a, ULL b) {
    asm("fma.rn.f32x2 %0, %1, %2, %0;" : "+l"(d) : "l"(a), "l"(b));
}
__device__ __forceinline__ ULL mul2(ULL a, ULL b) {
    ULL d;
    asm("mul.rn.f32x2 %0, %1, %2;" : "=l"(d) : "l"(a), "l"(b));
    return d;
}
__device__ __forceinline__ void prefetch_l2(const void* p) {
    asm volatile("prefetch.global.L2 [%0];" :: "l"(p));
}

// ---------------- kernel 0: tiled transpose W -> Wt (64 blocks) --------------
__global__ void transpose_kernel(const float* __restrict__ W) {
    __shared__ float tile[32][33];
    const int bx = blockIdx.x & 7;        // f-tile
    const int by = blockIdx.x >> 3;       // o-tile
    const int tx = threadIdx.x & 31;
    const int ty = threadIdx.x >> 5;      // 0..7
#pragma unroll
    for (int i = 0; i < 4; ++i)
        tile[ty + i * 8][tx] = W[(size_t)(by * 32 + ty + i * 8) * FF + bx * 32 + tx];
    __syncthreads();
#pragma unroll
    for (int i = 0; i < 4; ++i)
        g_Wt[(size_t)(bx * 32 + ty + i * 8) * FF + by * 32 + tx] = tile[tx][ty + i * 8];
}

// ---------------- kernel 1: Wh = h @ W^T ; fused s1 = Wh.a1, s2 = Wh.a2 ------
// Block: 256 threads, 64 rows x 256 cols, K tiled by 64.
// Lane m owns cols (4m..4m+3) and (128+4m..128+4m+3); a warp tiles all 256
// cols, so each warp owns rows r0..r0+7 completely -> s1/s2 via shfl reduce.
__global__ __launch_bounds__(256, 2) void wh_kernel(const float* __restrict__ h,
                                                    const float* __restrict__ a) {
    extern __shared__ char sm[];
    ULL*   h2   = (ULL*)sm;               // [64][64]
    float* Wt_s = (float*)(sm + 32768);   // [64][256]

    const int t    = threadIdx.x;
    const int row0 = blockIdx.x * 64;     // flat row over B*N
    const int r0   = (t >> 5) * 8;
    const int m    = t & 31;

    ULL acc[8][4];
#pragma unroll
    for (int rr = 0; rr < 8; ++rr)
#pragma unroll
        for (int k = 0; k < 4; ++k) acc[rr][k] = 0ULL;

    for (int kt = 0; kt < 4; ++kt) {
        const int k0 = kt * 64;
        __syncthreads();
        // fully unrolled staging: front-batched LDGs (MLP)
#pragma unroll
        for (int i = 0; i < 4; ++i) {
            int idx = t + i * 256;
            int r  = idx >> 4;
            int c4 = (idx & 15) << 2;
            float4 v = *(const float4*)(h + (size_t)(row0 + r) * FF + k0 + c4);
            ulonglong2* d = (ulonglong2*)&h2[r * 64 + c4];
            ulonglong2 p0; p0.x = dup_f32(v.x); p0.y = dup_f32(v.y);
            ulonglong2 p1; p1.x = dup_f32(v.z); p1.y = dup_f32(v.w);
            d[0] = p0; d[1] = p1;
        }
#pragma unroll
        for (int i = 0; i < 16; ++i) {
            int idx = t + i * 256;
            int r  = idx >> 6;
            int c4 = (idx & 63) << 2;
            *(float4*)&Wt_s[r * FF + c4] =
                *(const float4*)&g_Wt[(size_t)(k0 + r) * FF + c4];
        }
        __syncthreads();
#pragma unroll 8
        for (int kk = 0; kk < 64; ++kk) {
            ULL hv[8];
#pragma unroll
            for (int rr = 0; rr < 8; ++rr) hv[rr] = h2[(r0 + rr) * 64 + kk];
            const ulonglong2* wp = (const ulonglong2*)(Wt_s + kk * FF);
            ulonglong2 wa = wp[m];
            ulonglong2 wb = wp[m + 32];
#pragma unroll
            for (int rr = 0; rr < 8; ++rr) {
                fma2(acc[rr][0], hv[rr], wa.x);
                fma2(acc[rr][1], hv[rr], wa.y);
                fma2(acc[rr][2], hv[rr], wb.x);
                fma2(acc[rr][3], hv[rr], wb.y);
            }
        }
    }

#pragma unroll
    for (int rr = 0; rr < 8; ++rr) {
        size_t base = (size_t)(row0 + r0 + rr) * FF;
        ulonglong2 oa, ob;
        oa.x = acc[rr][0]; oa.y = acc[rr][1];
        ob.x = acc[rr][2]; ob.y = acc[rr][3];
        *(ulonglong2*)&g_Wh[base + 4 * m]       = oa;
        *(ulonglong2*)&g_Wh[base + 128 + 4 * m] = ob;
    }

    // fused s1 = Wh.a1, s2 = Wh.a2
    {
        float4 a1lo = *(const float4*)(a + 4 * m);
        float4 a1hi = *(const float4*)(a + 128 + 4 * m);
        float4 a2lo = *(const float4*)(a + FF + 4 * m);
        float4 a2hi = *(const float4*)(a + FF + 128 + 4 * m);
#pragma unroll
        for (int rr = 0; rr < 8; ++rr) {
            float2 c0 = *(float2*)&acc[rr][0];
            float2 c1 = *(float2*)&acc[rr][1];
            float2 c2 = *(float2*)&acc[rr][2];
            float2 c3 = *(float2*)&acc[rr][3];
            float s1 = c0.x*a1lo.x + c0.y*a1lo.y + c1.x*a1lo.z + c1.y*a1lo.w
                     + c2.x*a1hi.x + c2.y*a1hi.y + c3.x*a1hi.z + c3.y*a1hi.w;
            float s2 = c0.x*a2lo.x + c0.y*a2lo.y + c1.x*a2lo.z + c1.y*a2lo.w
                     + c2.x*a2hi.x + c2.y*a2hi.y + c3.x*a2hi.z + c3.y*a2hi.w;
#pragma unroll
            for (int d = 16; d > 0; d >>= 1) {
                s1 += __shfl_xor_sync(0xffffffffu, s1, d);
                s2 += __shfl_xor_sync(0xffffffffu, s2, d);
            }
            if (m == 0) {
                g_s1[row0 + r0 + rr] = s1;
                g_s2[row0 + r0 + rr] = s2;
            }
        }
    }
}

// ---------------- kernel 2: split-KV masked softmax + P@Wh partials ----------
// Grid: (32 row-tiles, 8 batches, NSPLIT). Block: 256 threads.
// Each CTA processes JT=8 j-tiles, writing unnormalized acc + (m,l) partials.
// adj loads for the CURRENT tile are issued before the staging barrier so
// their DRAM/L2 latency overlaps the Wh tile staging.
__global__ __launch_bounds__(256, 2) void attn_kernel(const int* __restrict__ adj) {
    extern __shared__ char sm[];
    float* Wh_s    = (float*)sm;                  // 65536 B
    ULL*   p2      = (ULL*)(sm + 65536);          // 32768 B
    float* s2_s    = (float*)(sm + 98304);        // 256 B
    float* m_row   = (float*)(sm + 98560);        // 256 B
    float* l_row   = (float*)(sm + 98816);        // 256 B
    float* alpha_s = (float*)(sm + 99072);        // 256 B  (total 99328)

    const int t    = threadIdx.x;
    const int b    = blockIdx.y;
    const int gi0  = blockIdx.x * 64;
    const int half = blockIdx.z;                  // split index 0..NSPLIT-1
    const int t0   = half * JT;                   // first j-tile

    const int sr  = t >> 2;
    const int sj0 = (t & 3) * 16;
    const float s1v = g_s1[b * NN + gi0 + sr];
    const int* adj_row = adj + ((size_t)b * NN + gi0 + sr) * NN;

    const int r0 = (t >> 5) * 8;
    const int m  = t & 31;

    prefetch_l2(adj_row + t0 * 64 + sj0);

    ULL acc[8][4];
#pragma unroll
    for (int rr = 0; rr < 8; ++rr)
#pragma unroll
        for (int k = 0; k < 4; ++k) acc[rr][k] = 0ULL;

    if (t < 64) { m_row[t] = -1e30f; l_row[t] = 0.f; }

    for (int tile = t0; tile < t0 + JT; ++tile) {
        const int gj0 = tile * 64;

        // issue adj loads for THIS tile before staging: latency hides under
        // the Wh_s fill + barrier below
        const int4* ap = (const int4*)(adj_row + gj0 + sj0);
        int4 av0 = ap[0], av1 = ap[1], av2 = ap[2], av3 = ap[3];

        __syncthreads();   // previous accum done; smem free
        // fully unrolled staging: front-batched LDGs (MLP=16)
#pragma unroll
        for (int i = 0; i < 16; ++i) {
            int idx = t + i * 256;
            int r  = idx >> 6;
            int c4 = (idx & 63) << 2;
            *(float4*)&Wh_s[r * FF + c4] =
                *(const float4*)&g_Wh[((size_t)b * NN + gj0 + r) * FF + c4];
        }
        if (t < 64) s2_s[t] = g_s2[b * NN + gj0 + t];
        __syncthreads();

        // pass 1: masked scores + quad row max (adj already in registers)
        float ev[16];
        float lmax = -1e30f;
        {
            int aa[16] = { av0.x, av0.y, av0.z, av0.w,
                           av1.x, av1.y, av1.z, av1.w,
                           av2.x, av2.y, av2.z, av2.w,
                           av3.x, av3.y, av3.z, av3.w };
#pragma unroll
            for (int q = 0; q < 16; ++q) {
                int j = sj0 + q;
                float x = s1v + s2_s[j];
                float e = fmaxf(x, LRA * x);     // leaky relu
                if (aa[q] == 0) e = -1e30f;      // mask
                ev[q] = e;
                lmax = fmaxf(lmax, e);
            }
        }
        lmax = fmaxf(lmax, __shfl_xor_sync(0xffffffffu, lmax, 1));
        lmax = fmaxf(lmax, __shfl_xor_sync(0xffffffffu, lmax, 2));
        // quad-local mn (clamped: all-masked tiles keep mn finite, masked p -> 0)
        float mo = m_row[sr];
        float mn = fmaxf(fmaxf(mo, lmax), -1e20f);
        if ((t & 3) == 0) {
            float al = __expf(mo - mn);
            m_row[sr] = mn; alpha_s[sr] = al;
            l_row[sr] *= al;
        }

        // pass 2: p = exp(e - mn), duplicated (STS.128)
        {
            float ps = 0.f;
#pragma unroll
            for (int q = 0; q < 16; q += 2) {
                float pa = __expf(ev[q]     - mn);
                float pb = __expf(ev[q + 1] - mn);
                ps += pa + pb;
                ulonglong2 pk; pk.x = dup_f32(pa); pk.y = dup_f32(pb);
                *(ulonglong2*)&p2[sr * 64 + sj0 + q] = pk;
            }
            ps += __shfl_xor_sync(0xffffffffu, ps, 1);
            ps += __shfl_xor_sync(0xffffffffu, ps, 2);
            if ((t & 3) == 0) l_row[sr] += ps;
        }
        __syncthreads();

        if (tile + 1 < t0 + JT) prefetch_l2(adj_row + gj0 + 64 + sj0);

        // accumulation: acc = acc*alpha + P * Wh_tile (f32x2)
#pragma unroll
        for (int rr = 0; rr < 8; ++rr) {
            ULL a2 = dup_f32(alpha_s[r0 + rr]);
#pragma unroll
            for (int k = 0; k < 4; ++k) acc[rr][k] = mul2(acc[rr][k], a2);
        }
#pragma unroll 8
        for (int j = 0; j < 64; ++j) {
            ULL pv[8];
#pragma unroll
            for (int rr = 0; rr < 8; ++rr) pv[rr] = p2[(r0 + rr) * 64 + j];
            const ulonglong2* wp = (const ulonglong2*)(Wh_s + j * FF);
            ulonglong2 wa = wp[m];
            ulonglong2 wb = wp[m + 32];
#pragma unroll
            for (int rr = 0; rr < 8; ++rr) {
                fma2(acc[rr][0], pv[rr], wa.x);
                fma2(acc[rr][1], pv[rr], wa.y);
                fma2(acc[rr][2], pv[rr], wb.x);
                fma2(acc[rr][3], pv[rr], wb.y);
            }
        }
    }
    __syncthreads();

    // epilogue: write unnormalized partial acc + (m,l)
    const int fbase = b * NN + gi0;
#pragma unroll
    for (int rr = 0; rr < 8; ++rr) {
        float* dst = g_pacc[half][fbase + r0 + rr];
        ulonglong2 oa, ob;
        oa.x = acc[rr][0]; oa.y = acc[rr][1];
        ob.x = acc[rr][2]; ob.y = acc[rr][3];
        *(ulonglong2*)&dst[4 * m]       = oa;
        *(ulonglong2*)&dst[128 + 4 * m] = ob;
    }
    if (t < 64) {
        g_pm[half][fbase + t] = m_row[t];   // finite (>= -1e20)
        g_pl[half][fbase + t] = l_row[t];
    }
}

// ---------------- kernel 3: combine split-KV partials ------------------------
// Warp per row; lane handles cols lane*8..lane*8+7.
__global__ void combine_kernel(float* __restrict__ out) {
    int row  = (blockIdx.x * blockDim.x + threadIdx.x) >> 5;
    int lane = threadIdx.x & 31;
    if (row >= BB * NN) return;

    float mM = -1e30f;
    float mv[NSPLIT];
#pragma unroll
    for (int s = 0; s < NSPLIT; ++s) { mv[s] = g_pm[s][row]; mM = fmaxf(mM, mv[s]); }
    float denom = 0.f;
    float sc[NSPLIT];
#pragma unroll
    for (int s = 0; s < NSPLIT; ++s) {
        sc[s] = __expf(mv[s] - mM);
        denom += g_pl[s][row] * sc[s];
    }
    float inv = (denom > 0.f) ? 1.0f / denom : 0.f;

    float4 n0 = make_float4(0.f, 0.f, 0.f, 0.f);
    float4 n1 = make_float4(0.f, 0.f, 0.f, 0.f);
#pragma unroll
    for (int s = 0; s < NSPLIT; ++s) {
        const float* src = g_pacc[s][row] + lane * 8;
        float4 p0 = *(const float4*)(src);
        float4 p1 = *(const float4*)(src + 4);
        float f = sc[s];
        n0.x += p0.x * f; n0.y += p0.y * f; n0.z += p0.z * f; n0.w += p0.w * f;
        n1.x += p1.x * f; n1.y += p1.y * f; n1.z += p1.z * f; n1.w += p1.w * f;
    }
    n0.x *= inv; n0.y *= inv; n0.z *= inv; n0.w *= inv;
    n1.x *= inv; n1.y *= inv; n1.z *= inv; n1.w *= inv;
    float* dst = out + (size_t)row * FF + lane * 8;
    *(float4*)(dst)     = n0;
    *(float4*)(dst + 4) = n1;
}

// ---------------- launch ------------------------------------------------------
extern "C" void kernel_launch(void* const* d_in, const int* in_sizes, int n_in,
                              void* d_out, int out_size) {
    const float* h   = (const float*)d_in[0];
    const int*   adj = (const int*)d_in[1];
    const float* W   = (const float*)d_in[2];
    const float* a   = (const float*)d_in[3];
    float* out = (float*)d_out;
    (void)in_sizes; (void)n_in; (void)out_size;

    cudaFuncSetAttribute(wh_kernel,   cudaFuncAttributeMaxDynamicSharedMemorySize, 98304);
    cudaFuncSetAttribute(attn_kernel, cudaFuncAttributeMaxDynamicSharedMemorySize, 99328);

    transpose_kernel<<<64, 256>>>(W);
    wh_kernel<<<(BB * NN) / 64, 256, 98304>>>(h, a);
    attn_kernel<<<dim3(32, BB, NSPLIT), 256, 99328>>>(adj);
    combine_kernel<<<(BB * NN) / 8, 256>>>(out);
}

// round 16
// speedup vs baseline: 2.4994x; 2.4994x over previous
#include <cuda_runtime.h>
#include <cuda_fp16.h>
#include <mma.h>
#include <cstdint>
#include <cstddef>

using namespace nvcuda;

// Problem constants
#define BB 8
#define NN 2048
#define FF 256
#define LRA 0.2f

typedef unsigned long long ULL;

// ---------------- scratch (device globals; no allocations allowed) ------------
__device__ __half g_Wh16[BB * NN * FF];   // 8 MB fp16 Wh (V operand, row-major)
__device__ float  g_s1[BB * NN];
__device__ float  g_s2[BB * NN];
__device__ float  g_mn[BB * NN];          // per-row softmax max (finite, >= -1e20)
__device__ float  g_Wt[FF * FF];          // W transposed

// ---------------- helpers -----------------------------------------------------
__device__ __forceinline__ ULL dup_f32(float x) {
    ULL r; unsigned u = __float_as_uint(x);
    asm("mov.b64 %0, {%1, %1};" : "=l"(r) : "r"(u));
    return r;
}
__device__ __forceinline__ void fma2(ULL& d, ULL a, ULL b) {
    asm("fma.rn.f32x2 %0, %1, %2, %0;" : "+l"(d) : "l"(a), "l"(b));
}
__device__ __forceinline__ void prefetch_l2(const void* p) {
    asm volatile("prefetch.global.L2 [%0];" :: "l"(p));
}

// ---------------- kernel 0: tiled transpose W -> Wt ---------------------------
__global__ void transpose_kernel(const float* __restrict__ W) {
    __shared__ float tile[32][33];
    const int bx = blockIdx.x & 7, by = blockIdx.x >> 3;
    const int tx = threadIdx.x & 31, ty = threadIdx.x >> 5;
#pragma unroll
    for (int i = 0; i < 4; ++i)
        tile[ty + i * 8][tx] = W[(size_t)(by * 32 + ty + i * 8) * FF + bx * 32 + tx];
    __syncthreads();
#pragma unroll
    for (int i = 0; i < 4; ++i)
        g_Wt[(size_t)(bx * 32 + ty + i * 8) * FF + by * 32 + tx] = tile[tx][ty + i * 8];
}

// ---------------- kernel 1: Wh = h @ W^T (fp32 math) ; fp16 store ; s1/s2 -----
// Lane m owns cols (4m..4m+3) and (128+4m..128+4m+3); a warp tiles all 256
// cols, so each warp owns rows r0..r0+7 completely -> s1/s2 via shfl reduce.
__global__ __launch_bounds__(256, 2) void wh_kernel(const float* __restrict__ h,
                                                    const float* __restrict__ a) {
    extern __shared__ char sm[];
    ULL*   h2   = (ULL*)sm;               // [64][64]
    float* Wt_s = (float*)(sm + 32768);   // [64][256]
    const int t    = threadIdx.x;
    const int row0 = blockIdx.x * 64;
    const int r0   = (t >> 5) * 8;
    const int m    = t & 31;

    ULL acc[8][4];
#pragma unroll
    for (int rr = 0; rr < 8; ++rr)
#pragma unroll
        for (int k = 0; k < 4; ++k) acc[rr][k] = 0ULL;

    for (int kt = 0; kt < 4; ++kt) {
        const int k0 = kt * 64;
        __syncthreads();
#pragma unroll
        for (int i = 0; i < 4; ++i) {
            int idx = t + i * 256;
            int r = idx >> 4, c4 = (idx & 15) << 2;
            float4 v = *(const float4*)(h + (size_t)(row0 + r) * FF + k0 + c4);
            ulonglong2* d = (ulonglong2*)&h2[r * 64 + c4];
            ulonglong2 p0; p0.x = dup_f32(v.x); p0.y = dup_f32(v.y);
            ulonglong2 p1; p1.x = dup_f32(v.z); p1.y = dup_f32(v.w);
            d[0] = p0; d[1] = p1;
        }
#pragma unroll
        for (int i = 0; i < 16; ++i) {
            int idx = t + i * 256;
            int r = idx >> 6, c4 = (idx & 63) << 2;
            *(float4*)&Wt_s[r * FF + c4] = *(const float4*)&g_Wt[(size_t)(k0 + r) * FF + c4];
        }
        __syncthreads();
#pragma unroll 8
        for (int kk = 0; kk < 64; ++kk) {
            ULL hv[8];
#pragma unroll
            for (int rr = 0; rr < 8; ++rr) hv[rr] = h2[(r0 + rr) * 64 + kk];
            const ulonglong2* wp = (const ulonglong2*)(Wt_s + kk * FF);
            ulonglong2 wa = wp[m], wb = wp[m + 32];
#pragma unroll
            for (int rr = 0; rr < 8; ++rr) {
                fma2(acc[rr][0], hv[rr], wa.x);
                fma2(acc[rr][1], hv[rr], wa.y);
                fma2(acc[rr][2], hv[rr], wb.x);
                fma2(acc[rr][3], hv[rr], wb.y);
            }
        }
    }
    // store Wh as fp16 (V operand), and fused s1/s2 from fp32 accs
    {
        float4 a1lo = *(const float4*)(a + 4 * m);
        float4 a1hi = *(const float4*)(a + 128 + 4 * m);
        float4 a2lo = *(const float4*)(a + FF + 4 * m);
        float4 a2hi = *(const float4*)(a + FF + 128 + 4 * m);
#pragma unroll
        for (int rr = 0; rr < 8; ++rr) {
            float2 c0 = *(float2*)&acc[rr][0];
            float2 c1 = *(float2*)&acc[rr][1];
            float2 c2 = *(float2*)&acc[rr][2];
            float2 c3 = *(float2*)&acc[rr][3];
            size_t base = (size_t)(row0 + r0 + rr) * FF;
            __half2 h01 = __float22half2_rn(make_float2(c0.x, c0.y));
            __half2 h23 = __float22half2_rn(make_float2(c1.x, c1.y));
            __half2 h45 = __float22half2_rn(make_float2(c2.x, c2.y));
            __half2 h67 = __float22half2_rn(make_float2(c3.x, c3.y));
            *(__half2*)&g_Wh16[base + 4 * m]           = h01;
            *(__half2*)&g_Wh16[base + 4 * m + 2]       = h23;
            *(__half2*)&g_Wh16[base + 128 + 4 * m]     = h45;
            *(__half2*)&g_Wh16[base + 128 + 4 * m + 2] = h67;
            float s1 = c0.x*a1lo.x + c0.y*a1lo.y + c1.x*a1lo.z + c1.y*a1lo.w
                     + c2.x*a1hi.x + c2.y*a1hi.y + c3.x*a1hi.z + c3.y*a1hi.w;
            float s2 = c0.x*a2lo.x + c0.y*a2lo.y + c1.x*a2lo.z + c1.y*a2lo.w
                     + c2.x*a2hi.x + c2.y*a2hi.y + c3.x*a2hi.z + c3.y*a2hi.w;
#pragma unroll
            for (int d = 16; d > 0; d >>= 1) {
                s1 += __shfl_xor_sync(0xffffffffu, s1, d);
                s2 += __shfl_xor_sync(0xffffffffu, s2, d);
            }
            if (m == 0) { g_s1[row0 + r0 + rr] = s1; g_s2[row0 + r0 + rr] = s2; }
        }
    }
}

// ---------------- kernel 2: masked row-max prepass ----------------------------
// mn_i = clamp(lrelu(s1_i + max_{j:adj=1} s2_j), -1e20). lrelu monotone => exact;
// pass-2 scores then satisfy p = exp(e - mn) <= 1 (no fp16 overflow).
__global__ void maxpass_kernel(const int* __restrict__ adj) {
    const int w = threadIdx.x >> 5, lane = threadIdx.x & 31;
    const int row = blockIdx.x * 8 + w;
    const int b = row >> 11;
    const int4*   ar  = (const int4*)(adj + (size_t)row * NN);
    const float4* s2b = (const float4*)(g_s2 + b * NN);
    float mx = -1e30f;
#pragma unroll 4
    for (int q = 0; q < 16; ++q) {
        int4 a4 = ar[q * 32 + lane];
        float4 s4 = s2b[q * 32 + lane];
        if (a4.x) mx = fmaxf(mx, s4.x);
        if (a4.y) mx = fmaxf(mx, s4.y);
        if (a4.z) mx = fmaxf(mx, s4.z);
        if (a4.w) mx = fmaxf(mx, s4.w);
    }
#pragma unroll
    for (int d = 16; d > 0; d >>= 1) mx = fmaxf(mx, __shfl_xor_sync(0xffffffffu, mx, d));
    if (lane == 0) {
        float x = g_s1[row] + mx;
        float e = fmaxf(x, LRA * x);
        g_mn[row] = fmaxf(e, -1e20f);
    }
}

// ---------------- kernel 3: fp16 WMMA flash attention -------------------------
// Grid (16, 8) = 128 CTAs (one per SM). CTA: 128 rows x 256 cols, 32 j-tiles.
// Fixed per-row max => no rescaling; fp32 wmma accumulators live in registers.
// Next tile's adj is L2-prefetched under the wmma phase (adj = only DRAM stream).
// SMEM: P [128][72] fp16 @0 (18432B), B [64][264] fp16 @18432 (33792B),
//       s2 @52224 (8192B), l_row @60416 (512B), obuf 8x1KB @60928. Tot 69120B.
#define PS 72
#define BS 264
#define SMEM_ATTN 69120
__global__ __launch_bounds__(256, 1)
void attn_wmma_kernel(const int* __restrict__ adj, float* __restrict__ out) {
    extern __shared__ char sm[];
    __half* P      = (__half*)sm;
    __half* B      = (__half*)(sm + 18432);
    float*  s2_all = (float*)(sm + 52224);
    float*  l_row  = (float*)(sm + 60416);
    float*  obuf   = (float*)(sm + 60928);

    const int t   = threadIdx.x;
    const int b   = blockIdx.y;
    const int gi0 = blockIdx.x * 128;
    const int wid  = t >> 5;
    const int lane = t & 31;

#pragma unroll
    for (int i = 0; i < 2; ++i)
        ((float4*)s2_all)[t + i * 256] = ((const float4*)(g_s2 + b * NN))[t + i * 256];
    if (t < 128) l_row[t] = 0.f;

    const int sr  = t >> 1;               // local row 0..127 (score phase)
    const int sjl = (t & 1) * 32;         // j-half within tile
    const float s1v = g_s1[b * NN + gi0 + sr];
    const float mnv = g_mn[b * NN + gi0 + sr];
    const int* adj_row = adj + ((size_t)b * NN + gi0 + sr) * NN;
    const __half* wsrc = g_Wh16 + (size_t)b * NN * FF;

    // warm L2 for the first adj tile
    prefetch_l2(adj_row + sjl);

    wmma::fragment<wmma::accumulator, 16, 16, 16, float> acc[16];
#pragma unroll
    for (int n = 0; n < 16; ++n) wmma::fill_fragment(acc[n], 0.0f);
    const int r0 = wid * 16;              // wmma row strip

    for (int tile = 0; tile < 32; ++tile) {
        const int gj0 = tile * 64;
        __syncthreads();   // previous tile's P/B consumed
        // stage B = Wh16 rows [gj0..gj0+63] x 256 cols (row-major, ldm 264)
#pragma unroll
        for (int i = 0; i < 8; ++i) {
            int idx = t + i * 256;
            int r = idx >> 5, c8 = (idx & 31) << 3;
            *(int4*)&B[r * BS + c8] = *(const int4*)(wsrc + (size_t)(gj0 + r) * FF + c8);
        }
        // scores -> P [128][72] fp16 ; l accumulation (p <= 1 exactly)
        {
            const int4* ap = (const int4*)(adj_row + gj0 + sjl);
            float ps = 0.f;
#pragma unroll
            for (int q8 = 0; q8 < 4; ++q8) {
                int4 a0 = ap[q8 * 2], a1 = ap[q8 * 2 + 1];
                int aa[8] = { a0.x, a0.y, a0.z, a0.w, a1.x, a1.y, a1.z, a1.w };
                __half2 hp[4];
#pragma unroll
                for (int u = 0; u < 4; ++u) {
                    int j0 = gj0 + sjl + q8 * 8 + 2 * u;
                    float x0 = s1v + s2_all[j0];
                    float x1 = s1v + s2_all[j0 + 1];
                    float e0 = fmaxf(x0, LRA * x0); if (aa[2 * u] == 0)     e0 = -1e30f;
                    float e1 = fmaxf(x1, LRA * x1); if (aa[2 * u + 1] == 0) e1 = -1e30f;
                    float p0 = __expf(e0 - mnv);
                    float p1 = __expf(e1 - mnv);
                    ps += p0 + p1;
                    hp[u] = __float22half2_rn(make_float2(p0, p1));
                }
                *(int4*)&P[sr * PS + sjl + q8 * 8] = *(int4*)hp;
            }
            ps += __shfl_xor_sync(0xffffffffu, ps, 1);
            if (!(t & 1)) l_row[sr] += ps;
        }
        __syncthreads();   // P/B visible

        // prefetch next tile's adj into L2; latency hidden under wmma below
        if (tile + 1 < 32) prefetch_l2(adj_row + gj0 + 64 + sjl);

        // wmma: strip r0..r0+15, all 256 cols, K=64
#pragma unroll
        for (int k = 0; k < 4; ++k) {
            wmma::fragment<wmma::matrix_a, 16, 16, 16, __half, wmma::row_major> fa;
            wmma::load_matrix_sync(fa, P + r0 * PS + k * 16, PS);
#pragma unroll
            for (int n = 0; n < 16; ++n) {
                wmma::fragment<wmma::matrix_b, 16, 16, 16, __half, wmma::row_major> fb;
                wmma::load_matrix_sync(fb, B + (k * 16) * BS + n * 16, BS);
                wmma::mma_sync(acc[n], fa, fb, acc[n]);
            }
        }
    }
    __syncthreads();

    // epilogue: per-warp store frags -> smem buf -> scale by 1/l -> global
    const int er = lane >> 1, ec0 = (lane & 1) * 8;
    float l = l_row[r0 + er];
    float inv = (l > 0.f) ? 1.0f / l : 0.f;
    float* ob = obuf + wid * 256;
    float* dst = out + ((size_t)b * NN + gi0 + r0 + er) * FF + ec0;
#pragma unroll
    for (int n = 0; n < 16; ++n) {
        wmma::store_matrix_sync(ob, acc[n], 16, wmma::mem_row_major);
        __syncwarp();
        float4 v0 = *(float4*)&ob[er * 16 + ec0];
        float4 v1 = *(float4*)&ob[er * 16 + ec0 + 4];
        v0.x *= inv; v0.y *= inv; v0.z *= inv; v0.w *= inv;
        v1.x *= inv; v1.y *= inv; v1.z *= inv; v1.w *= inv;
        *(float4*)(dst + n * 16)     = v0;
        *(float4*)(dst + n * 16 + 4) = v1;
        __syncwarp();
    }
}

// ---------------- launch ------------------------------------------------------
extern "C" void kernel_launch(void* const* d_in, const int* in_sizes, int n_in,
                              void* d_out, int out_size) {
    const float* h   = (const float*)d_in[0];
    const int*   adj = (const int*)d_in[1];
    const float* W   = (const float*)d_in[2];
    const float* a   = (const float*)d_in[3];
    float* out = (float*)d_out;
    (void)in_sizes; (void)n_in; (void)out_size;

    cudaFuncSetAttribute(wh_kernel,        cudaFuncAttributeMaxDynamicSharedMemorySize, 98304);
    cudaFuncSetAttribute(attn_wmma_kernel, cudaFuncAttributeMaxDynamicSharedMemorySize, SMEM_ATTN);

    transpose_kernel<<<64, 256>>>(W);
    wh_kernel<<<(BB * NN) / 64, 256, 98304>>>(h, a);
    maxpass_kernel<<<(BB * NN) / 8, 256>>>(adj);
    attn_wmma_kernel<<<dim3(NN / 128, BB), 256, SMEM_ATTN>>>(adj, out);
}